// round 8
// baseline (speedup 1.0000x reference)
#include <cuda_runtime.h>
#include <cstdint>

// SoftCountPixels: Y[b,p] = (1/(H*W)) * sum_{h,w} exp(-||x[b,:,h,w] - P[p,:]||_2 / 0.6)
// x: (16, 3, 256, 256) f32 planar; P: (32, 3) f32; out: (16, 32) f32
//
// exp(-d/0.6) = ex2(-sqrt(K2*d^2)), K2=(log2e/0.6)^2: pre-scaled quadratic
// form; |.| and neg fold into MUFU source modifiers when ptxas allows.
// R8: clean SCALAR inner loop (f32x2 experiment showed no fusion benefit and
// bloated the ALU pipe with pack/unpack movs), 592-block perfectly balanced
// flat partition (148 SMs x 4 CTAs), and a single kernel: atomicAdd into
// zero-initialized __device__ scratch, last block (ticket) scales into d_out
// and resets state for the next graph replay. No zero_out prologue kernel.

#define B 16
#define HW (256 * 256)
#define HW4 (HW / 4)             // 16384 = 2^14 float4 per channel plane
#define HW4_SHIFT 14
#define NPRO 32
#define PPT 4                    // protos per thread
#define PGROUPS (NPRO / PPT)     // 8
#define NCOMBO (B * PGROUPS)     // 128
#define THREADS 256
#define NBLOCKS (148 * 4)        // 592: one perfectly balanced wave @ 4 CTA/SM
#define TOTAL_UNITS ((unsigned long long)NCOMBO * HW4)   // 2,097,152

#define K2 5.781580510735007f    // (log2(e)/0.6)^2

__device__ float    g_scratch[B * NPRO];   // zero-initialized at module load
__device__ unsigned g_ticket = 0;

__device__ __forceinline__ float fast_sqrt(float v) {
    float r;
    asm("sqrt.approx.f32 %0, %1;" : "=f"(r) : "f"(v));
    return r;
}
__device__ __forceinline__ float fast_ex2(float v) {
    float r;
    asm("ex2.approx.f32 %0, %1;" : "=f"(r) : "f"(v));
    return r;
}

__device__ __forceinline__ float pair_term(float cck, float xxk,
                                           float q0, float q1, float q2,
                                           float x0, float x1, float x2) {
    float t = cck + xxk;
    t = fmaf(q0, x0, t);
    t = fmaf(q1, x1, t);
    t = fmaf(q2, x2, t);
    return fast_ex2(-fast_sqrt(fabsf(t)));
}

__global__ __launch_bounds__(THREADS, 4)
void softcount_kernel(const float* __restrict__ x,
                      const float* __restrict__ P,
                      float* __restrict__ out) {
    const int tid  = threadIdx.x;
    const int lane = tid & 31;
    const unsigned long long bid = blockIdx.x;

    // This block's contiguous range of global float4-units.
    unsigned long long u0 = (bid * TOTAL_UNITS) / NBLOCKS;
    const unsigned long long u1 = ((bid + 1) * TOTAL_UNITS) / NBLOCKS;

    while (u0 < u1) {
        const unsigned combo = (unsigned)(u0 >> HW4_SHIFT);   // 0..127
        const unsigned long long combo_end = (unsigned long long)(combo + 1) << HW4_SHIFT;
        const unsigned long long seg_end = (u1 < combo_end) ? u1 : combo_end;

        const int pg = (int)(combo >> 4);   // 0..7
        const int b  = (int)(combo & 15);   // 0..15

        // Per-thread proto constants, pre-scaled by K2.
        float q0[PPT], q1[PPT], q2[PPT], cck[PPT], acc[PPT];
#pragma unroll
        for (int i = 0; i < PPT; i++) {
            const int p = pg * PPT + i;
            const float p0 = __ldg(&P[p * 3 + 0]);
            const float p1 = __ldg(&P[p * 3 + 1]);
            const float p2 = __ldg(&P[p * 3 + 2]);
            q0[i] = -2.0f * K2 * p0;
            q1[i] = -2.0f * K2 * p1;
            q2[i] = -2.0f * K2 * p2;
            cck[i] = K2 * (p0 * p0 + p1 * p1 + p2 * p2);
            acc[i] = 0.0f;
        }

        // Local float4 index range within this combo's image.
        const int vs = (int)(u0 & (HW4 - 1));
        const int ve = (int)(seg_end - ((unsigned long long)combo << HW4_SHIFT));

        const float4* xb = (const float4*)(x + (size_t)b * 3 * HW);

        for (int v = vs + tid; v < ve; v += THREADS) {
            const float4 c0 = xb[v];              // channel 0, pixels 0..3
            const float4 c1 = xb[v + HW4];        // channel 1
            const float4 c2 = xb[v + 2 * HW4];    // channel 2

            {   // pixel 0
                float xx = c0.x * c0.x; xx = fmaf(c1.x, c1.x, xx); xx = fmaf(c2.x, c2.x, xx);
                const float xxk = K2 * xx;
#pragma unroll
                for (int i = 0; i < PPT; i++)
                    acc[i] += pair_term(cck[i], xxk, q0[i], q1[i], q2[i], c0.x, c1.x, c2.x);
            }
            {   // pixel 1
                float xx = c0.y * c0.y; xx = fmaf(c1.y, c1.y, xx); xx = fmaf(c2.y, c2.y, xx);
                const float xxk = K2 * xx;
#pragma unroll
                for (int i = 0; i < PPT; i++)
                    acc[i] += pair_term(cck[i], xxk, q0[i], q1[i], q2[i], c0.y, c1.y, c2.y);
            }
            {   // pixel 2
                float xx = c0.z * c0.z; xx = fmaf(c1.z, c1.z, xx); xx = fmaf(c2.z, c2.z, xx);
                const float xxk = K2 * xx;
#pragma unroll
                for (int i = 0; i < PPT; i++)
                    acc[i] += pair_term(cck[i], xxk, q0[i], q1[i], q2[i], c0.z, c1.z, c2.z);
            }
            {   // pixel 3
                float xx = c0.w * c0.w; xx = fmaf(c1.w, c1.w, xx); xx = fmaf(c2.w, c2.w, xx);
                const float xxk = K2 * xx;
#pragma unroll
                for (int i = 0; i < PPT; i++)
                    acc[i] += pair_term(cck[i], xxk, q0[i], q1[i], q2[i], c0.w, c1.w, c2.w);
            }
        }

        // Flush this segment into scratch: warp shuffle + 1 atomic per (warp, proto).
#pragma unroll
        for (int i = 0; i < PPT; i++) {
            float v = acc[i];
#pragma unroll
            for (int off = 16; off > 0; off >>= 1)
                v += __shfl_xor_sync(0xFFFFFFFFu, v, off);
            if (lane == 0)
                atomicAdd(&g_scratch[b * NPRO + pg * PPT + i], v);
        }

        u0 = seg_end;
    }

    // ---- last-block finisher: scale scratch into d_out, reset state ----
    __threadfence();
    __shared__ unsigned is_last;
    if (tid == 0) {
        const unsigned t = atomicAdd(&g_ticket, 1u);
        is_last = (t == NBLOCKS - 1) ? 1u : 0u;
    }
    __syncthreads();
    if (is_last) {
        __threadfence();  // ensure visibility of all blocks' scratch atomics
        for (int i = tid; i < B * NPRO; i += THREADS) {
            out[i] = g_scratch[i] * (1.0f / (float)HW);
            g_scratch[i] = 0.0f;          // reset for next graph replay
        }
        __syncthreads();
        if (tid == 0) g_ticket = 0u;      // reset ticket
    }
}

extern "C" void kernel_launch(void* const* d_in, const int* in_sizes, int n_in,
                              void* d_out, int out_size) {
    const float* x = (const float*)d_in[0];
    const float* P = (const float*)d_in[1];
    float* out = (float*)d_out;

    softcount_kernel<<<NBLOCKS, THREADS>>>(x, P, out);
}

// round 9
// speedup vs baseline: 1.0920x; 1.0920x over previous
#include <cuda_runtime.h>
#include <cstdint>

// SoftCountPixels: Y[b,p] = (1/(H*W)) * sum_{h,w} exp(-||x[b,:,h,w] - P[p,:]||_2 / 0.6)
// x: (16, 3, 256, 256) f32 planar; P: (32, 3) f32; out: (16, 32) f32
//
// exp(-d/0.6) = ex2(-sqrt(K2*d^2)), K2=(log2e/0.6)^2 (pre-scaled quadratic form).
// R9: best-measured R7 body (packed f32x2 pair math, 444-block balanced flat
// partition) plus: (1) fabs removed via +3e-5 epsilon in cck — worst-case fp
// cancellation in the quadratic form is ~6e-6 (terms <= ~50, 4-op chain), so
// s > 0 always; induced error in exp is <= ~2e-5 relative for typical r and
// vanishingly weighted for tiny r. (2) sqrt->neg->ex2 fused in ONE asm block
// so the neg folds into the MUFU source modifier. (3) unroll-2 pixel loop.
// (4) single kernel: scratch + ticket finisher replaces the zero-out prologue.

#define B 16
#define HW (256 * 256)
#define HW4 (HW / 4)             // 16384 = 2^14 vec4 per channel plane
#define HW4_SHIFT 14
#define NPRO 32
#define PPT 4                    // protos per thread
#define PGROUPS (NPRO / PPT)     // 8
#define NCOMBO (B * PGROUPS)     // 128
#define THREADS 256
#define NBLOCKS 444              // 148 SMs * 3 CTAs -> one perfectly balanced wave
#define TOTAL_UNITS ((unsigned long long)NCOMBO * HW4)   // 2,097,152

#define K2 5.781580510735007f    // (log2(e)/0.6)^2
#define EPS_S 3e-5f              // positivity guard for the quadratic form

__device__ float    g_scratch[B * NPRO];   // zero-initialized at module load
__device__ unsigned g_ticket = 0;

// exp2(-sqrt(s)) for s > 0, one fused MUFU.SQRT -> MUFU.EX2(-src) chain.
__device__ __forceinline__ float exp_neg_sqrt(float s) {
    float e;
    asm("{\n\t"
        ".reg .f32 r;\n\t"
        "sqrt.approx.f32 r, %1;\n\t"
        "neg.f32 r, r;\n\t"
        "ex2.approx.f32 %0, r;\n\t"
        "}" : "=f"(e) : "f"(s));
    return e;
}

// ---- packed f32x2 helpers ----
__device__ __forceinline__ uint64_t pack2(float lo, float hi) {
    uint64_t r;
    asm("mov.b64 %0, {%1, %2};" : "=l"(r) : "f"(lo), "f"(hi));
    return r;
}
__device__ __forceinline__ void unpack2(uint64_t v, float& lo, float& hi) {
    asm("mov.b64 {%0, %1}, %2;" : "=f"(lo), "=f"(hi) : "l"(v));
}
__device__ __forceinline__ uint64_t fma2(uint64_t a, uint64_t b, uint64_t c) {
    uint64_t r;
    asm("fma.rn.f32x2 %0, %1, %2, %3;" : "=l"(r) : "l"(a), "l"(b), "l"(c));
    return r;
}
__device__ __forceinline__ uint64_t add2(uint64_t a, uint64_t b) {
    uint64_t r;
    asm("add.rn.f32x2 %0, %1, %2;" : "=l"(r) : "l"(a), "l"(b));
    return r;
}
__device__ __forceinline__ uint64_t mul2(uint64_t a, uint64_t b) {
    uint64_t r;
    asm("mul.rn.f32x2 %0, %1, %2;" : "=l"(r) : "l"(a), "l"(b));
    return r;
}

__global__ __launch_bounds__(THREADS, 3)
void softcount_kernel(const float* __restrict__ x,
                      const float* __restrict__ P,
                      float* __restrict__ out) {
    const int tid  = threadIdx.x;
    const int lane = tid & 31;
    const unsigned long long bid = blockIdx.x;

    // This block's contiguous range of global vec4-units.
    unsigned long long u0 = (bid * TOTAL_UNITS) / NBLOCKS;
    const unsigned long long u1 = ((bid + 1) * TOTAL_UNITS) / NBLOCKS;

    while (u0 < u1) {
        const unsigned combo = (unsigned)(u0 >> HW4_SHIFT);   // 0..127
        const unsigned long long combo_end = (unsigned long long)(combo + 1) << HW4_SHIFT;
        const unsigned long long seg_end = (u1 < combo_end) ? u1 : combo_end;

        const int pg = (int)(combo >> 4);   // 0..7
        const int b  = (int)(combo & 15);   // 0..15

        // Packed (broadcast) per-proto constants, pre-scaled by K2.
        uint64_t qk0[PPT], qk1[PPT], qk2[PPT], cck[PPT];
        float acc[PPT];
#pragma unroll
        for (int i = 0; i < PPT; i++) {
            const int p = pg * PPT + i;
            const float p0 = __ldg(&P[p * 3 + 0]);
            const float p1 = __ldg(&P[p * 3 + 1]);
            const float p2 = __ldg(&P[p * 3 + 2]);
            const float q0 = -2.0f * K2 * p0;
            const float q1 = -2.0f * K2 * p1;
            const float q2 = -2.0f * K2 * p2;
            const float cc = K2 * (p0 * p0 + p1 * p1 + p2 * p2) + EPS_S;
            qk0[i] = pack2(q0, q0);
            qk1[i] = pack2(q1, q1);
            qk2[i] = pack2(q2, q2);
            cck[i] = pack2(cc, cc);
            acc[i] = 0.0f;
        }
        const uint64_t K2_2 = pack2(K2, K2);

        // Local vec4 index range within this combo's image.
        const int vs = (int)(u0 & (HW4 - 1));
        const int ve = (int)(seg_end - ((unsigned long long)combo << HW4_SHIFT));

        const ulonglong2* xb = (const ulonglong2*)(x + (size_t)b * 3 * HW);

#pragma unroll 2
        for (int v = vs + tid; v < ve; v += THREADS) {
            const ulonglong2 c0 = xb[v];              // ch0: pixels(0,1),(2,3) packed
            const ulonglong2 c1 = xb[v + HW4];        // ch1
            const ulonglong2 c2 = xb[v + 2 * HW4];    // ch2

            // ---- pixel pair (0,1) ----
            {
                const uint64_t X0 = c0.x, X1 = c1.x, X2 = c2.x;
                uint64_t xx = mul2(X0, X0);
                xx = fma2(X1, X1, xx);
                xx = fma2(X2, X2, xx);
                const uint64_t xxk = mul2(K2_2, xx);
#pragma unroll
                for (int i = 0; i < PPT; i++) {
                    uint64_t t = add2(cck[i], xxk);
                    t = fma2(qk0[i], X0, t);
                    t = fma2(qk1[i], X1, t);
                    t = fma2(qk2[i], X2, t);
                    float ta, tb;
                    unpack2(t, ta, tb);
                    acc[i] += exp_neg_sqrt(ta);
                    acc[i] += exp_neg_sqrt(tb);
                }
            }
            // ---- pixel pair (2,3) ----
            {
                const uint64_t X0 = c0.y, X1 = c1.y, X2 = c2.y;
                uint64_t xx = mul2(X0, X0);
                xx = fma2(X1, X1, xx);
                xx = fma2(X2, X2, xx);
                const uint64_t xxk = mul2(K2_2, xx);
#pragma unroll
                for (int i = 0; i < PPT; i++) {
                    uint64_t t = add2(cck[i], xxk);
                    t = fma2(qk0[i], X0, t);
                    t = fma2(qk1[i], X1, t);
                    t = fma2(qk2[i], X2, t);
                    float ta, tb;
                    unpack2(t, ta, tb);
                    acc[i] += exp_neg_sqrt(ta);
                    acc[i] += exp_neg_sqrt(tb);
                }
            }
        }

        // Flush this segment into scratch: warp shuffle + 1 atomic per (warp, proto).
#pragma unroll
        for (int i = 0; i < PPT; i++) {
            float v = acc[i];
#pragma unroll
            for (int off = 16; off > 0; off >>= 1)
                v += __shfl_xor_sync(0xFFFFFFFFu, v, off);
            if (lane == 0)
                atomicAdd(&g_scratch[b * NPRO + pg * PPT + i], v);
        }

        u0 = seg_end;
    }

    // ---- last-block finisher: scale scratch into d_out, reset state ----
    __threadfence();
    __shared__ unsigned is_last;
    if (tid == 0) {
        const unsigned t = atomicAdd(&g_ticket, 1u);
        is_last = (t == NBLOCKS - 1) ? 1u : 0u;
    }
    __syncthreads();
    if (is_last) {
        __threadfence();  // all blocks' scratch atomics visible
        for (int i = tid; i < B * NPRO; i += THREADS) {
            out[i] = g_scratch[i] * (1.0f / (float)HW);
            g_scratch[i] = 0.0f;          // reset for next graph replay
        }
        __syncthreads();
        if (tid == 0) g_ticket = 0u;      // reset ticket
    }
}

extern "C" void kernel_launch(void* const* d_in, const int* in_sizes, int n_in,
                              void* d_out, int out_size) {
    const float* x = (const float*)d_in[0];
    const float* P = (const float*)d_in[1];
    float* out = (float*)d_out;

    softcount_kernel<<<NBLOCKS, THREADS>>>(x, P, out);
}